// round 17
// baseline (speedup 1.0000x reference)
#include <cuda_runtime.h>
#include <math.h>

#define N_LEVELS      16
#define HASHMAP_SIZE  (1u << 19)
#define HASH_MASK     (HASHMAP_SIZE - 1u)
#define P2            2654435761u
#define P3            805459861u

// level-0/1 dense tables cached in shared memory
#define L0_R1      17
#define L0_ENTRIES (L0_R1 * L0_R1 * L0_R1)          // 4913
#define L1_R1      23
#define L1_ENTRIES (L1_R1 * L1_R1 * L1_R1)          // 12167
#define SMEM_ENTRIES (L0_ENTRIES + L1_ENTRIES)      // 17080 float2 = 136.6 KB

#define BLOCK_THREADS 1024
#define GRID_BLOCKS   148

struct ResTable {
    int res[N_LEVELS];
};

// Persistent grid: 148 blocks x 1024 threads, 1 block/SM (smem-limited).
// Each block preloads level-0/1 tables into smem once, then its warps loop
// over points (8 lanes per point, 4 points per warp, R14 body).
__global__ void __launch_bounds__(BLOCK_THREADS)
hashenc_kernel(const float* __restrict__ pos,
               const float* __restrict__ emb,
               float* __restrict__ out,
               ResTable rt,
               int n_points)
{
    extern __shared__ float2 stab[];   // [0,4913): level0, [4913,17080): level1

    // ---- preload coarse tables (once per block) ----
    {
        const float2* __restrict__ t0 = reinterpret_cast<const float2*>(emb);
        const float2* __restrict__ t1 = t0 + HASHMAP_SIZE;
        for (int i = threadIdx.x; i < L0_ENTRIES; i += BLOCK_THREADS)
            stab[i] = t0[i];
        for (int i = threadIdx.x; i < L1_ENTRIES; i += BLOCK_THREADS)
            stab[L0_ENTRIES + i] = t1[i];
    }
    __syncthreads();

    const int lane = threadIdx.x & 31;
    const int c    = lane & 7;          // corner id: (i<<2)|(j<<1)|k
    const int sub  = lane >> 3;         // point slot within warp (0..3)
    const int gwarp = (blockIdx.x * BLOCK_THREADS + threadIdx.x) >> 5;
    const int stride = GRID_BLOCKS * (BLOCK_THREADS / 32) * 4;   // points per sweep

    const unsigned bi = (c >> 2) & 1;
    const unsigned bj = (c >> 1) & 1;
    const unsigned bk =  c       & 1;

    const float sxw = bi ? 1.f : -1.f, oxw = bi ? 0.f : 1.f;
    const float syw = bj ? 1.f : -1.f, oyw = bj ? 0.f : 1.f;
    const float szw = bk ? 1.f : -1.f, ozw = bk ? 0.f : 1.f;

    // warp-uniform loop bound; lanes guard with `valid`
    for (int pbase = gwarp * 4; pbase < n_points; pbase += stride) {
        const int p     = pbase + sub;
        const bool valid = (p < n_points);
        const int  pp    = valid ? p : 0;

        const float px = pos[pp * 3 + 0];
        const float py = pos[pp * 3 + 1];
        const float pz = pos[pp * 3 + 2];

        float acc0 = 0.f, acc1 = 0.f, acc2 = 0.f, acc3 = 0.f;

#pragma unroll
        for (int l = 0; l < N_LEVELS; ++l) {
            const int   res  = rt.res[l];
            const float fres = (float)res;

            const float sx = px * fres, sy = py * fres, sz = pz * fres;
            const float fx = floorf(sx), fy = floorf(sy), fz = floorf(sz);
            const float wx = sx - fx,   wy = sy - fy,   wz = sz - fz;

            const unsigned ux = (unsigned)(int)fx + bi;
            const unsigned uy = (unsigned)(int)fy + bj;
            const unsigned uz = (unsigned)(int)fz + bk;

            const unsigned r1 = (unsigned)(res + 1);
            const bool dense =
                ((long long)r1 * (long long)r1 * (long long)r1) <= (long long)HASHMAP_SIZE;

            unsigned idx;
            if (dense) {
                idx = ux * (r1 * r1) + uy * r1 + uz;
            } else {
                idx = (ux ^ (uy * P2) ^ (uz * P3)) & HASH_MASK;
            }

            float2 f;
            if (l == 0) {
                f = stab[idx];                         // smem: level 0
            } else if (l == 1) {
                f = stab[L0_ENTRIES + idx];            // smem: level 1
            } else {
                const float2* __restrict__ table =
                    reinterpret_cast<const float2*>(emb) + (size_t)l * HASHMAP_SIZE;
                f = __ldcg(&table[idx]);               // L2 only
            }

            const float ax = fmaf(sxw, wx, oxw);
            const float ay = fmaf(syw, wy, oyw);
            const float az = fmaf(szw, wz, ozw);
            const float w  = ax * ay * az;

            float v0 = f.x * w;
            float v1 = f.y * w;

            v0 += __shfl_xor_sync(0xffffffffu, v0, 4);
            v1 += __shfl_xor_sync(0xffffffffu, v1, 4);
            v0 += __shfl_xor_sync(0xffffffffu, v0, 2);
            v1 += __shfl_xor_sync(0xffffffffu, v1, 2);
            v0 += __shfl_xor_sync(0xffffffffu, v0, 1);
            v1 += __shfl_xor_sync(0xffffffffu, v1, 1);

            if ((l >> 1) == c) {
                if (l & 1) { acc2 = v0; acc3 = v1; }
                else       { acc0 = v0; acc1 = v1; }
            }
        }

        if (valid) {
            float4* __restrict__ o4 = reinterpret_cast<float4*>(out);
            o4[(size_t)p * 8 + c] = make_float4(acc0, acc1, acc2, acc3);
        }
    }
}

extern "C" void kernel_launch(void* const* d_in, const int* in_sizes, int n_in,
                              void* d_out, int out_size)
{
    const float* positions  = (const float*)d_in[0];   // [N_POINTS, 3] f32
    const float* embeddings = (const float*)d_in[1];   // [16, 2^19, 2] f32
    float*       out        = (float*)d_out;           // [N_POINTS, 32] f32

    const int n_points = in_sizes[0] / 3;

    // Mirror numpy exactly in double precision (libm exp/log/pow)
    ResTable rt;
    const double scale = exp((log(2048.0) - log(16.0)) / 15.0);
    for (int l = 0; l < N_LEVELS; ++l) {
        rt.res[l] = (int)floor(16.0 * pow(scale, (double)l));
    }

    const int smem_bytes = SMEM_ENTRIES * (int)sizeof(float2);   // ~136.6 KB
    cudaFuncSetAttribute(hashenc_kernel,
                         cudaFuncAttributeMaxDynamicSharedMemorySize, smem_bytes);

    hashenc_kernel<<<GRID_BLOCKS, BLOCK_THREADS, smem_bytes>>>(
        positions, embeddings, out, rt, n_points);
}